// round 4
// baseline (speedup 1.0000x reference)
#include <cuda_runtime.h>
#include <cuda_bf16.h>

// LIF over time: x[B=256, T=130, N=4096] f32 -> spikes same shape.
// Recurrence per (b,n): mem = mem*DECAY*(1-spike_prev) + x[t]; spike = mem > THRESH.
// One 4-neuron column group per thread (full 262144-thread grid -> high occupancy),
// 2-deep software prefetch (2 outstanding LDG.128 per thread). Streaming cache
// hints: every byte is touch-once.

#define LIF_THRESH 0.6f
#define LIF_DECAY  0.2f

__global__ __launch_bounds__(256)
void lif_kernel(const float4* __restrict__ x, float4* __restrict__ out) {
    constexpr int T    = 130;
    constexpr int ROW4 = 4096 / 4;   // 1024 float4 per (b,t) row

    const int idx = blockIdx.x * blockDim.x + threadIdx.x;   // 0 .. 256*1024-1
    const int b   = idx >> 10;         // / 1024
    const int c   = idx & (ROW4 - 1);  // % 1024

    const size_t base = (size_t)b * (size_t)(T * ROW4) + (size_t)c;
    const float4* __restrict__ xp = x   + base;
    float4*       __restrict__ op = out + base;

    float m0 = 0.f, m1 = 0.f, m2 = 0.f, m3 = 0.f;
    float f0 = LIF_DECAY, f1 = LIF_DECAY, f2 = LIF_DECAY, f3 = LIF_DECAY;

    // 2-deep prefetch pipeline
    float4 cur = __ldcs(xp);
    float4 nx1 = __ldcs(xp + ROW4);

    #pragma unroll 2
    for (int t = 0; t < T - 2; ++t) {
        float4 nx2 = __ldcs(xp + (size_t)(t + 2) * ROW4);

        m0 = fmaf(m0, f0, cur.x);
        m1 = fmaf(m1, f1, cur.y);
        m2 = fmaf(m2, f2, cur.z);
        m3 = fmaf(m3, f3, cur.w);

        float4 sp;
        sp.x = (m0 > LIF_THRESH) ? 1.0f : 0.0f;
        sp.y = (m1 > LIF_THRESH) ? 1.0f : 0.0f;
        sp.z = (m2 > LIF_THRESH) ? 1.0f : 0.0f;
        sp.w = (m3 > LIF_THRESH) ? 1.0f : 0.0f;

        f0 = (m0 > LIF_THRESH) ? 0.0f : LIF_DECAY;
        f1 = (m1 > LIF_THRESH) ? 0.0f : LIF_DECAY;
        f2 = (m2 > LIF_THRESH) ? 0.0f : LIF_DECAY;
        f3 = (m3 > LIF_THRESH) ? 0.0f : LIF_DECAY;

        __stcs(op + (size_t)t * ROW4, sp);

        cur = nx1;
        nx1 = nx2;
    }

    // tail: t = T-2 and t = T-1, no further prefetch
    #pragma unroll
    for (int k = 0; k < 2; ++k) {
        const int t = T - 2 + k;

        m0 = fmaf(m0, f0, cur.x);
        m1 = fmaf(m1, f1, cur.y);
        m2 = fmaf(m2, f2, cur.z);
        m3 = fmaf(m3, f3, cur.w);

        float4 sp;
        sp.x = (m0 > LIF_THRESH) ? 1.0f : 0.0f;
        sp.y = (m1 > LIF_THRESH) ? 1.0f : 0.0f;
        sp.z = (m2 > LIF_THRESH) ? 1.0f : 0.0f;
        sp.w = (m3 > LIF_THRESH) ? 1.0f : 0.0f;

        f0 = (m0 > LIF_THRESH) ? 0.0f : LIF_DECAY;
        f1 = (m1 > LIF_THRESH) ? 0.0f : LIF_DECAY;
        f2 = (m2 > LIF_THRESH) ? 0.0f : LIF_DECAY;
        f3 = (m3 > LIF_THRESH) ? 0.0f : LIF_DECAY;

        __stcs(op + (size_t)t * ROW4, sp);

        cur = nx1;
    }
}

extern "C" void kernel_launch(void* const* d_in, const int* in_sizes, int n_in,
                              void* d_out, int out_size) {
    const float4* x   = (const float4*)d_in[0];
    float4*       out = (float4*)d_out;

    constexpr int B = 256, N = 4096;
    const int threads = 256;
    const int total   = B * (N / 4);          // 262144 threads
    const int blocks  = total / threads;      // 1024

    lif_kernel<<<blocks, threads>>>(x, out);
}

// round 5
// speedup vs baseline: 1.0574x; 1.0574x over previous
#include <cuda_runtime.h>
#include <cuda_bf16.h>

// LIF over time: x[B=256, T=130, N=4096] f32 -> spikes same shape.
// Recurrence per (b,n): mem = mem*DECAY*(1-spike_prev) + x[t]; spike = mem > THRESH.
// Each thread owns TWO 4-neuron column groups (c, c+512) of one batch row ->
// 2 outstanding LDG.128 per thread via 1-deep prefetch on each group.
// 128-thread blocks (1024 CTAs) for fine-grained SM load balance.
// Streaming cache hints: every byte is touch-once.

#define LIF_THRESH 0.6f
#define LIF_DECAY  0.2f

__global__ __launch_bounds__(128)
void lif_kernel(const float4* __restrict__ x, float4* __restrict__ out) {
    constexpr int T    = 130;
    constexpr int ROW4 = 4096 / 4;     // 1024 float4 per (b,t) row
    constexpr int HALF = ROW4 / 2;     // 512: column split per thread

    const int idx = blockIdx.x * blockDim.x + threadIdx.x;   // 0 .. 256*512-1
    const int b   = idx >> 9;          // / 512
    const int c   = idx & (HALF - 1);  // % 512

    const size_t base = (size_t)b * (size_t)(T * ROW4) + (size_t)c;
    const float4* __restrict__ xp = x   + base;
    float4*       __restrict__ op = out + base;

    // group A: column c, group B: column c+HALF
    float a0 = 0.f, a1 = 0.f, a2 = 0.f, a3 = 0.f;
    float b0 = 0.f, b1 = 0.f, b2 = 0.f, b3 = 0.f;
    float fa0 = LIF_DECAY, fa1 = LIF_DECAY, fa2 = LIF_DECAY, fa3 = LIF_DECAY;
    float fb0 = LIF_DECAY, fb1 = LIF_DECAY, fb2 = LIF_DECAY, fb3 = LIF_DECAY;

    float4 curA = __ldcs(xp);
    float4 curB = __ldcs(xp + HALF);

    #pragma unroll 2
    for (int t = 0; t < T - 1; ++t) {
        const size_t nofs = (size_t)(t + 1) * ROW4;
        // two independent prefetches in flight while the update chains run
        float4 nxtA = __ldcs(xp + nofs);
        float4 nxtB = __ldcs(xp + nofs + HALF);

        a0 = fmaf(a0, fa0, curA.x);
        a1 = fmaf(a1, fa1, curA.y);
        a2 = fmaf(a2, fa2, curA.z);
        a3 = fmaf(a3, fa3, curA.w);
        b0 = fmaf(b0, fb0, curB.x);
        b1 = fmaf(b1, fb1, curB.y);
        b2 = fmaf(b2, fb2, curB.z);
        b3 = fmaf(b3, fb3, curB.w);

        float4 spA, spB;
        spA.x = (a0 > LIF_THRESH) ? 1.0f : 0.0f;
        spA.y = (a1 > LIF_THRESH) ? 1.0f : 0.0f;
        spA.z = (a2 > LIF_THRESH) ? 1.0f : 0.0f;
        spA.w = (a3 > LIF_THRESH) ? 1.0f : 0.0f;
        spB.x = (b0 > LIF_THRESH) ? 1.0f : 0.0f;
        spB.y = (b1 > LIF_THRESH) ? 1.0f : 0.0f;
        spB.z = (b2 > LIF_THRESH) ? 1.0f : 0.0f;
        spB.w = (b3 > LIF_THRESH) ? 1.0f : 0.0f;

        fa0 = (a0 > LIF_THRESH) ? 0.0f : LIF_DECAY;
        fa1 = (a1 > LIF_THRESH) ? 0.0f : LIF_DECAY;
        fa2 = (a2 > LIF_THRESH) ? 0.0f : LIF_DECAY;
        fa3 = (a3 > LIF_THRESH) ? 0.0f : LIF_DECAY;
        fb0 = (b0 > LIF_THRESH) ? 0.0f : LIF_DECAY;
        fb1 = (b1 > LIF_THRESH) ? 0.0f : LIF_DECAY;
        fb2 = (b2 > LIF_THRESH) ? 0.0f : LIF_DECAY;
        fb3 = (b3 > LIF_THRESH) ? 0.0f : LIF_DECAY;

        const size_t ofs = (size_t)t * ROW4;
        __stcs(op + ofs,        spA);
        __stcs(op + ofs + HALF, spB);

        curA = nxtA;
        curB = nxtB;
    }

    // tail iteration (t = T-1), no prefetch
    {
        a0 = fmaf(a0, fa0, curA.x);
        a1 = fmaf(a1, fa1, curA.y);
        a2 = fmaf(a2, fa2, curA.z);
        a3 = fmaf(a3, fa3, curA.w);
        b0 = fmaf(b0, fb0, curB.x);
        b1 = fmaf(b1, fb1, curB.y);
        b2 = fmaf(b2, fb2, curB.z);
        b3 = fmaf(b3, fb3, curB.w);

        float4 spA, spB;
        spA.x = (a0 > LIF_THRESH) ? 1.0f : 0.0f;
        spA.y = (a1 > LIF_THRESH) ? 1.0f : 0.0f;
        spA.z = (a2 > LIF_THRESH) ? 1.0f : 0.0f;
        spA.w = (a3 > LIF_THRESH) ? 1.0f : 0.0f;
        spB.x = (b0 > LIF_THRESH) ? 1.0f : 0.0f;
        spB.y = (b1 > LIF_THRESH) ? 1.0f : 0.0f;
        spB.z = (b2 > LIF_THRESH) ? 1.0f : 0.0f;
        spB.w = (b3 > LIF_THRESH) ? 1.0f : 0.0f;

        const size_t ofs = (size_t)(T - 1) * ROW4;
        __stcs(op + ofs,        spA);
        __stcs(op + ofs + HALF, spB);
    }
}

extern "C" void kernel_launch(void* const* d_in, const int* in_sizes, int n_in,
                              void* d_out, int out_size) {
    const float4* x   = (const float4*)d_in[0];
    float4*       out = (float4*)d_out;

    constexpr int B = 256, N = 4096;
    const int threads = 128;
    const int total   = B * (N / 8);          // 131072 threads (2 groups each)
    const int blocks  = total / threads;      // 1024

    lif_kernel<<<blocks, threads>>>(x, out);
}